// round 11
// baseline (speedup 1.0000x reference)
#include <cuda_runtime.h>
#include <cstddef>

// ---------------------------------------------------------------------------
// AttentionalLatentTrajectoryGenerator — single persistent kernel (1 graph
// node), fp32 f32x2-packed CUDA-core GEMMs, device-wide software barrier.
//
// Algebraic reductions:
//   * seq_len==1 attention => softmax == 1 => a = gin @ (Wv@Wo) + (bv@Wo+bo)
//   * gh0(t+1) = h1@Whh0 merged into the gi1 GEMM (same A = h1)
//   * gh1(t+1) = h2@Whh1 merged into the nz GEMM  (same A = h2)
// ---------------------------------------------------------------------------

#define NBLK 148
#define NTHR 256

namespace {
constexpr int HID = 1024;
constexpr int LAT = 256;
constexpr int BSZ = 64;
constexpr int H3  = 3 * HID;
}

// -------------------- device scratch (no allocations allowed) --------------
__device__ __align__(16) float S_Wvo[HID * HID];
__device__ __align__(16) float S_bvo[HID];
__device__ __align__(16) float S_a  [BSZ * HID];
__device__ __align__(16) float S_gi [BSZ * H3];
__device__ __align__(16) float S_gh0[BSZ * H3];
__device__ __align__(16) float S_gh1[BSZ * H3];
__device__ __align__(16) float S_h1 [BSZ * HID];
__device__ __align__(16) float S_h2 [BSZ * HID];
__device__ __align__(16) float S_gin[BSZ * HID];
__device__ __align__(16) float S_X1 [BSZ * HID];
__device__ __align__(16) float S_nz [BSZ * LAT];

// -------------------- device-wide barrier state ----------------------------
// g_count returns to 0 at every barrier => state is replay-invariant.
__device__ unsigned g_count = 0;
__device__ volatile unsigned g_gen = 0;

__device__ __forceinline__ void gsync() {
    __syncthreads();
    if (threadIdx.x == 0) {
        __threadfence();                       // publish this block's writes
        unsigned gen = g_gen;
        if (atomicAdd(&g_count, 1u) == NBLK - 1) {
            atomicExch(&g_count, 0u);
            __threadfence();
            g_gen = gen + 1;                   // release
        } else {
            while (g_gen == gen) { __nanosleep(32); }
        }
        __threadfence();                       // acquire
    }
    __syncthreads();
}

// -------------------- packed fp32x2 FMA (dual fp32 pipe) -------------------
__device__ __forceinline__ float2 f2fma(float2 a, float2 b, float2 c) {
    unsigned long long ra = *reinterpret_cast<unsigned long long*>(&a);
    unsigned long long rb = *reinterpret_cast<unsigned long long*>(&b);
    unsigned long long rc = *reinterpret_cast<unsigned long long*>(&c);
    unsigned long long rd;
    asm("fma.rn.f32x2 %0, %1, %2, %3;" : "=l"(rd) : "l"(ra), "l"(rb), "l"(rc));
    return *reinterpret_cast<float2*>(&rd);
}

// -------------------- shared-memory layout ---------------------------------
struct Smem {
    float2 As[32][66];     // [k][m] A value duplicated {a,a}; 16896 B
    float  Bs[32][36];     // [k][n]; 4608 B
    float  red[256];       // bvo reduction
};

// ---------------------------------------------------------------------------
// One 64x32 output tile: C[0..63, 0..31] = act(A[64,K] @ W[K,32] + bias).
// Pointers pre-offset by caller (A at row0/k0, W at k0/n0, C at row0/n0).
// NOTE: A, W intentionally NOT __restrict__ — they alias mutable buffers
// rewritten across barriers; must not become LDG.nc.
// ---------------------------------------------------------------------------
__device__ __noinline__ void gemm_tile(
    Smem* sm, const float* A, int lda, int K,
    const float* W, int ldw, const float* bias,
    float* C, int ldc, bool relu, float* C2, int ldc2)
{
    const int tid = threadIdx.x;
    const int tc = tid & 15, tr = tid >> 4;       // 16 col-groups x 16 row-groups
    const int ml = tr * 4, nl = tc * 2;           // TM=4, TN=2
    const int kq = tid & 7,  ma = tid >> 3;       // A-stage map
    const int c4 = tid & 7,  kr = tid >> 3;       // B-stage map (kr in [0,32))

    float2 acc0 = make_float2(0.f, 0.f), acc1 = acc0, acc2 = acc0, acc3 = acc0;

    for (int k0 = 0; k0 < K; k0 += 32) {
        // stage A tile (64x32), transposed + duplicated {a,a}
        #pragma unroll
        for (int r = 0; r < 2; r++) {
            int m = ma + r * 32;
            float4 v = *reinterpret_cast<const float4*>(
                &A[(size_t)m * lda + k0 + kq * 4]);
            sm->As[kq * 4 + 0][m] = make_float2(v.x, v.x);
            sm->As[kq * 4 + 1][m] = make_float2(v.y, v.y);
            sm->As[kq * 4 + 2][m] = make_float2(v.z, v.z);
            sm->As[kq * 4 + 3][m] = make_float2(v.w, v.w);
        }
        // stage B tile (32x32)
        *reinterpret_cast<float4*>(&sm->Bs[kr][c4 * 4]) =
            *reinterpret_cast<const float4*>(&W[(size_t)(k0 + kr) * ldw + c4 * 4]);
        __syncthreads();

        #pragma unroll
        for (int kk = 0; kk < 32; kk++) {
            float2 b  = *reinterpret_cast<const float2*>(&sm->Bs[kk][nl]);
            float4 a01 = *reinterpret_cast<const float4*>(&sm->As[kk][ml]);
            float4 a23 = *reinterpret_cast<const float4*>(&sm->As[kk][ml + 2]);
            acc0 = f2fma(make_float2(a01.x, a01.y), b, acc0);
            acc1 = f2fma(make_float2(a01.z, a01.w), b, acc1);
            acc2 = f2fma(make_float2(a23.x, a23.y), b, acc2);
            acc3 = f2fma(make_float2(a23.z, a23.w), b, acc3);
        }
        __syncthreads();
    }

    float2 bb = bias ? *reinterpret_cast<const float2*>(&bias[nl])
                     : make_float2(0.f, 0.f);
    float2 av[4] = {acc0, acc1, acc2, acc3};
    #pragma unroll
    for (int i = 0; i < 4; i++) {
        float2 v;
        v.x = av[i].x + bb.x;
        v.y = av[i].y + bb.y;
        if (relu) { v.x = fmaxf(v.x, 0.f); v.y = fmaxf(v.y, 0.f); }
        *reinterpret_cast<float2*>(&C[(size_t)(ml + i) * ldc + nl]) = v;
        if (C2)
            *reinterpret_cast<float2*>(&C2[(size_t)(ml + i) * ldc2 + nl]) = v;
    }
}

// -------------------- single-segment stage ---------------------------------
__device__ __forceinline__ void stage1(
    Smem* sm, const float* A, int lda, int K,
    const float* W, int ldw, const float* bias,
    float* C, int ldc, int ntiles, bool relu)
{
    for (int it = blockIdx.x; it < ntiles; it += NBLK)
        gemm_tile(sm, A, lda, K, W + it * 32, ldw,
                  bias ? bias + it * 32 : nullptr,
                  C + it * 32, ldc, relu, nullptr, 0);
}

// -------------------- two-segment stage (shared A) -------------------------
__device__ __forceinline__ void stage2seg(
    Smem* sm, const float* A, int lda, int K,
    const float* W0, int ldw0, const float* b0, float* C0, int ldc0, int nt0,
    float* C0b, int ldc0b,
    const float* W1, int ldw1, const float* b1, float* C1, int ldc1, int nt1)
{
    for (int it = blockIdx.x; it < nt0 + nt1; it += NBLK) {
        if (it < nt0)
            gemm_tile(sm, A, lda, K, W0 + it * 32, ldw0, b0 + it * 32,
                      C0 + it * 32, ldc0, false,
                      C0b ? C0b + it * 32 : nullptr, ldc0b);
        else {
            int j = it - nt0;
            gemm_tile(sm, A, lda, K, W1 + j * 32, ldw1, b1 + j * 32,
                      C1 + j * 32, ldc1, false, nullptr, 0);
        }
    }
}

// -------------------- GRU elementwise --------------------------------------
__device__ __forceinline__ void gru_stage(const float* gi, const float* gh,
                                          float* h)
{
    for (int i = blockIdx.x * NTHR + threadIdx.x; i < BSZ * HID;
         i += NBLK * NTHR) {
        int m = i >> 10, j = i & (HID - 1);
        int g = m * H3 + j;
        float r  = 1.f / (1.f + expf(-(gi[g] + gh[g])));
        float zz = 1.f / (1.f + expf(-(gi[g + HID] + gh[g + HID])));
        float nn = tanhf(gi[g + 2 * HID] + r * gh[g + 2 * HID]);
        h[i] = (1.f - zz) * nn + zz * h[i];
    }
}

// ---------------------------------------------------------------------------
__global__ void __launch_bounds__(NTHR, 1) traj_kernel(
    const float* z,
    const float* w1, const float* b1, const float* w2, const float* b2,
    const float* Wv, const float* bv, const float* Wo, const float* bo,
    const float* Wih0, const float* Whh0, const float* bih0, const float* bhh0,
    const float* Wih1, const float* Whh1, const float* bih1, const float* bhh1,
    const float* Wh, const float* bh,
    float* out, int T)
{
    __shared__ Smem sm;
    const int b = blockIdx.x;
    const int tid = threadIdx.x;
    const int ldo = T * LAT;

    // ================= prologue =================
    // Wvo = Wv @ Wo : 16 m-tiles x 32 n-tiles = 512 items
    for (int it = b; it < 512; it += NBLK) {
        int mi = it >> 5, ni = it & 31;
        gemm_tile(&sm, Wv + (size_t)mi * 64 * HID, HID, HID,
                  Wo + ni * 32, HID, nullptr,
                  S_Wvo + (size_t)mi * 64 * HID + ni * 32, HID,
                  false, nullptr, 0);
    }
    // bvo = bv @ Wo + bo : blocks 0..31, 32 cols each
    if (b < 32) {
        __syncthreads();
        int nl = tid & 31, ks = tid >> 5;          // 8 k-slices of 128
        const float* col = Wo + b * 32 + nl;
        float s = 0.f;
        for (int k = ks * 128; k < ks * 128 + 128; k++)
            s += bv[k] * col[(size_t)k * HID];
        sm.red[tid] = s;
        __syncthreads();
        if (tid < 32) {
            float t = bo[b * 32 + nl];
            #pragma unroll
            for (int q = 0; q < 8; q++) t += sm.red[nl + 32 * q];
            S_bvo[b * 32 + nl] = t;
        }
        __syncthreads();
    }
    gsync();

    // X1 = relu(z @ w1 + b1), K = LAT
    stage1(&sm, z, LAT, LAT, w1, HID, b1, S_X1, HID, 32, true);
    gsync();
    // gin = h0p = X1 @ w2 + b2  (no relu at init)
    stage1(&sm, S_X1, HID, HID, w2, HID, b2, S_gin, HID, 32, false);
    gsync();
    // h1 = h2 = h0p ; gh0 = h0p@Whh0+bhh0 ; gh1 = h0p@Whh1+bhh1
    for (int i = b * NTHR + tid; i < BSZ * HID / 4; i += NBLK * NTHR) {
        float4 v = reinterpret_cast<const float4*>(S_gin)[i];
        reinterpret_cast<float4*>(S_h1)[i] = v;
        reinterpret_cast<float4*>(S_h2)[i] = v;
    }
    stage2seg(&sm, S_gin, HID, HID,
              Whh0, H3, bhh0, S_gh0, H3, 96, nullptr, 0,
              Whh1, H3, bhh1, S_gh1, H3, 96);
    gsync();

    // ================= time loop =================
    for (int t = 0; t < T; t++) {
        // s1: a = gin @ Wvo + bvo
        stage1(&sm, S_gin, HID, HID, S_Wvo, HID, S_bvo, S_a, HID, 32, false);
        gsync();
        // s2: gi0 = a @ Wih0 + bih0
        stage1(&sm, S_a, HID, HID, Wih0, H3, bih0, S_gi, H3, 96, false);
        gsync();
        // gru0: h1 update
        gru_stage(S_gi, S_gh0, S_h1);
        gsync();
        // s4: [gi1 | gh0_next] = h1 @ [Wih1 | Whh0]
        stage2seg(&sm, S_h1, HID, HID,
                  Wih1, H3, bih1, S_gi, H3, 96, nullptr, 0,
                  Whh0, H3, bhh0, S_gh0, H3, 96);
        gsync();
        // gru1: h2 update
        gru_stage(S_gi, S_gh1, S_h2);
        gsync();
        // s6: [nz -> S_nz & out[:,t,:] | gh1_next] = h2 @ [Wh | Whh1]
        stage2seg(&sm, S_h2, HID, HID,
                  Wh, LAT, bh, S_nz, LAT, 8, out + (size_t)t * LAT, ldo,
                  Whh1, H3, bhh1, S_gh1, H3, 96);
        gsync();
        // s7: X1 = relu(nz @ w1 + b1), K = LAT
        stage1(&sm, S_nz, LAT, LAT, w1, HID, b1, S_X1, HID, 32, true);
        gsync();
        // s8: gin = relu(X1 @ w2 + b2)
        stage1(&sm, S_X1, HID, HID, w2, HID, b2, S_gin, HID, 32, true);
        gsync();
    }
}

// ---------------------------------------------------------------------------
extern "C" void kernel_launch(void* const* d_in, const int* in_sizes, int n_in,
                              void* d_out, int out_size)
{
    (void)in_sizes; (void)n_in;
    const float* z    = (const float*)d_in[0];
    // d_in[1] = max_len (device int32); T derived from out_size instead.
    const float* w1   = (const float*)d_in[2];
    const float* b1   = (const float*)d_in[3];
    const float* w2   = (const float*)d_in[4];
    const float* b2   = (const float*)d_in[5];
    // d_in[6..9] = Wq, bq, Wk, bk — dead (softmax over a single key == 1).
    const float* Wv   = (const float*)d_in[10];
    const float* bv   = (const float*)d_in[11];
    const float* Wo   = (const float*)d_in[12];
    const float* bo   = (const float*)d_in[13];
    const float* Wih0 = (const float*)d_in[14];
    const float* Whh0 = (const float*)d_in[15];
    const float* bih0 = (const float*)d_in[16];
    const float* bhh0 = (const float*)d_in[17];
    const float* Wih1 = (const float*)d_in[18];
    const float* Whh1 = (const float*)d_in[19];
    const float* bih1 = (const float*)d_in[20];
    const float* bhh1 = (const float*)d_in[21];
    const float* Wh   = (const float*)d_in[22];
    const float* bh   = (const float*)d_in[23];
    float* out = (float*)d_out;

    const int T = out_size / (BSZ * LAT);   // 128

    traj_kernel<<<NBLK, NTHR>>>(
        z, w1, b1, w2, b2, Wv, bv, Wo, bo,
        Wih0, Whh0, bih0, bhh0, Wih1, Whh1, bih1, bhh1,
        Wh, bh, out, T);
}

// round 12
// speedup vs baseline: 2.0846x; 2.0846x over previous
#include <cuda_runtime.h>
#include <cstddef>

// ---------------------------------------------------------------------------
// AttentionalLatentTrajectoryGenerator — persistent kernel, 64x64 fp32 tiles
// (TM4xTN4 scalar FFMA, 2B/MAC smem traffic), split-K=2 with consumer-side
// partial summation, co-packed stages, prefetch-double-buffered staging.
// ---------------------------------------------------------------------------

#define NBLK 148
#define NTHR 256

namespace {
constexpr int HID = 1024;
constexpr int LAT = 256;
constexpr int BSZ = 64;
constexpr int H3  = 3 * HID;
}

// -------------------- device scratch ---------------------------------------
__device__ __align__(16) float S_Wvo [HID * HID];
__device__ __align__(16) float S_bvo [HID];
__device__ __align__(16) float S_a_m [BSZ * HID];
__device__ __align__(16) float S_a_p [BSZ * HID];
__device__ __align__(16) float S_gi_m[BSZ * H3];
__device__ __align__(16) float S_gi_p[BSZ * H3];
__device__ __align__(16) float S_gh0m[BSZ * H3];
__device__ __align__(16) float S_gh0p[BSZ * H3];
__device__ __align__(16) float S_gh1m[BSZ * H3];
__device__ __align__(16) float S_gh1p[BSZ * H3];
__device__ __align__(16) float S_h1  [BSZ * HID];
__device__ __align__(16) float S_h2  [BSZ * HID];
__device__ __align__(16) float S_ginm[BSZ * HID];
__device__ __align__(16) float S_ginp[BSZ * HID];
__device__ __align__(16) float S_X1m [BSZ * HID];
__device__ __align__(16) float S_X1p [BSZ * HID];
__device__ __align__(16) float S_nzm [BSZ * LAT];
__device__ __align__(16) float S_nzp [BSZ * LAT];

// -------------------- device-wide barrier (replay-invariant) ----------------
__device__ unsigned g_count = 0;
__device__ volatile unsigned g_gen = 0;

__device__ __forceinline__ void gsync() {
    __syncthreads();
    if (threadIdx.x == 0) {
        __threadfence();
        unsigned gen = g_gen;
        if (atomicAdd(&g_count, 1u) == NBLK - 1) {
            atomicExch(&g_count, 0u);
            __threadfence();
            g_gen = gen + 1;
        } else {
            while (g_gen == gen) { __nanosleep(64); }
        }
        __threadfence();
    }
    __syncthreads();
}

// -------------------- shared memory ----------------------------------------
struct Smem {
    float As[32][68];   // [k][m]
    float Bs[32][68];   // [k][n]
    float red[256];
};

// ---------------------------------------------------------------------------
// One 64x64 tile: C = A_eff[64,Klen] @ W[Klen,64] (+bias).
// amode: 0 = A plain, 1 = A + A2, 2 = relu(A + A2).  No epilogue activation
// (split-K partials must stay linear; consumers apply relu after summing).
// Staging is register-prefetched to hide L2 latency.
// ---------------------------------------------------------------------------
__device__ __noinline__ void gemm_tile(
    Smem* sm, const float* A, const float* A2, int lda, int Klen, int amode,
    const float* W, int ldw, const float* bias, float* C, int ldc)
{
    const int tid = threadIdx.x;
    const int tc = tid & 15, tr = tid >> 4;
    const int ml = tr * 4, nl = tc * 4;
    const int am  = tid >> 2;            // A staging: row 0..63
    const int aq0 = (tid & 3) * 2;       // A staging: float4 col {aq0, aq0+1}
    const int bkr = tid >> 4;            // B staging: k-row base (+16 for r=1)
    const int bc4 = tid & 15;            // B staging: float4 col

    float acc[4][4];
    #pragma unroll
    for (int i = 0; i < 4; i++)
        #pragma unroll
        for (int j = 0; j < 4; j++) acc[i][j] = 0.f;

    float4 pa[2], pa2[2], pb[2];
    #pragma unroll
    for (int r = 0; r < 2; r++) {
        pa[r] = *(const float4*)&A[(size_t)am * lda + (aq0 + r) * 4];
        if (amode) pa2[r] = *(const float4*)&A2[(size_t)am * lda + (aq0 + r) * 4];
        pb[r] = *(const float4*)&W[(size_t)(bkr + r * 16) * ldw + bc4 * 4];
    }

    for (int k0 = 0; k0 < Klen; k0 += 32) {
        __syncthreads();                          // smem free (prev inner done)
        #pragma unroll
        for (int r = 0; r < 2; r++) {
            float4 v = pa[r];
            if (amode) {
                v.x += pa2[r].x; v.y += pa2[r].y;
                v.z += pa2[r].z; v.w += pa2[r].w;
            }
            if (amode == 2) {
                v.x = fmaxf(v.x, 0.f); v.y = fmaxf(v.y, 0.f);
                v.z = fmaxf(v.z, 0.f); v.w = fmaxf(v.w, 0.f);
            }
            const int q = aq0 + r;
            sm->As[q * 4 + 0][am] = v.x;
            sm->As[q * 4 + 1][am] = v.y;
            sm->As[q * 4 + 2][am] = v.z;
            sm->As[q * 4 + 3][am] = v.w;
            *(float4*)&sm->Bs[bkr + r * 16][bc4 * 4] = pb[r];
        }
        if (k0 + 32 < Klen) {                     // prefetch next k-tile
            const int kn = k0 + 32;
            #pragma unroll
            for (int r = 0; r < 2; r++) {
                pa[r] = *(const float4*)&A[(size_t)am * lda + kn + (aq0 + r) * 4];
                if (amode)
                    pa2[r] = *(const float4*)&A2[(size_t)am * lda + kn + (aq0 + r) * 4];
                pb[r] = *(const float4*)&W[(size_t)(kn + bkr + r * 16) * ldw + bc4 * 4];
            }
        }
        __syncthreads();                          // staged data visible

        #pragma unroll
        for (int kk = 0; kk < 32; kk++) {
            float4 a4 = *(const float4*)&sm->As[kk][ml];
            float4 b4 = *(const float4*)&sm->Bs[kk][nl];
            float av[4] = {a4.x, a4.y, a4.z, a4.w};
            float bv[4] = {b4.x, b4.y, b4.z, b4.w};
            #pragma unroll
            for (int i = 0; i < 4; i++)
                #pragma unroll
                for (int j = 0; j < 4; j++)
                    acc[i][j] += av[i] * bv[j];
        }
    }

    float4 bb = bias ? *(const float4*)&bias[nl] : make_float4(0.f, 0.f, 0.f, 0.f);
    #pragma unroll
    for (int i = 0; i < 4; i++) {
        float4 v;
        v.x = acc[i][0] + bb.x; v.y = acc[i][1] + bb.y;
        v.z = acc[i][2] + bb.z; v.w = acc[i][3] + bb.w;
        *(float4*)&C[(size_t)(ml + i) * ldc + nl] = v;
    }
}

// One split-K=2 work item j in [0, 2*ntiles): n = j>>1, k-half = j&1.
__device__ __forceinline__ void split_item(
    Smem* sm, int j, const float* A, const float* A2, int lda, int amode,
    int Ktot, const float* W, int ldw, const float* bias,
    float* Cm, float* Cp, int ldc)
{
    const int n0 = (j >> 1) * 64, kh = j & 1, Kh = Ktot >> 1, ko = kh * Kh;
    gemm_tile(sm, A + ko, A2 ? A2 + ko : nullptr, lda, Kh, amode,
              W + (size_t)ko * ldw + n0, ldw,
              kh ? nullptr : (bias + n0),
              (kh ? Cp : Cm) + n0, ldc);
}

// GRU elementwise (partials summed here): h = (1-z)*n + z*h
__device__ __forceinline__ void gru_stage(
    const float* gim, const float* gip, const float* ghm, const float* ghp,
    float* h)
{
    for (int i = blockIdx.x * NTHR + threadIdx.x; i < BSZ * HID;
         i += NBLK * NTHR) {
        int m = i >> 10, j = i & (HID - 1);
        int g = m * H3 + j;
        float ir = gim[g] + gip[g];
        float iz = gim[g + HID] + gip[g + HID];
        float in_ = gim[g + 2 * HID] + gip[g + 2 * HID];
        float hr = ghm[g] + ghp[g];
        float hz = ghm[g + HID] + ghp[g + HID];
        float hn = ghm[g + 2 * HID] + ghp[g + 2 * HID];
        float r  = 1.f / (1.f + expf(-(ir + hr)));
        float zz = 1.f / (1.f + expf(-(iz + hz)));
        float nn = tanhf(in_ + r * hn);
        h[i] = (1.f - zz) * nn + zz * h[i];
    }
}

// ---------------------------------------------------------------------------
__global__ void __launch_bounds__(NTHR, 1) traj_kernel(
    const float* z,
    const float* w1, const float* b1, const float* w2, const float* b2,
    const float* Wv, const float* bv, const float* Wo, const float* bo,
    const float* Wih0, const float* Whh0, const float* bih0, const float* bhh0,
    const float* Wih1, const float* Whh1, const float* bih1, const float* bhh1,
    const float* Wh, const float* bh,
    float* out, int T)
{
    __shared__ Smem sm;
    const int b = blockIdx.x;
    const int tid = threadIdx.x;
    const int ldo = T * LAT;

    // ===== P1: Wvo = Wv@Wo (256 tiles) + X1init = z@w1+b1 (16 tiles, raw) ===
    for (int it = b; it < 272; it += NBLK) {
        if (it < 256) {
            int mi = it >> 4, ni = it & 15;
            gemm_tile(&sm, Wv + (size_t)mi * 64 * HID, nullptr, HID, HID, 0,
                      Wo + ni * 64, HID, nullptr,
                      S_Wvo + (size_t)mi * 64 * HID + ni * 64, HID);
        } else {
            int ni = it - 256;
            gemm_tile(&sm, z, nullptr, LAT, LAT, 0,
                      w1 + ni * 64, HID, b1 + ni * 64, S_X1m + ni * 64, HID);
        }
    }
    for (int i = b * NTHR + tid; i < BSZ * HID; i += NBLK * NTHR) {
        S_X1p[i] = 0.f; S_ginp[i] = 0.f;     // unsplit producers => zero parts
    }
    gsync();

    // ===== P2: gin_m = h0p = relu(X1)@w2+b2 ; bvo = bv@Wo+bo ===============
    if (b < 16) {
        gemm_tile(&sm, S_X1m, S_X1p, HID, HID, 2,
                  w2 + b * 64, HID, b2 + b * 64, S_ginm + b * 64, HID);
    } else if (b < 48) {
        int nb = b - 16;
        int nlid = tid & 31, ks = tid >> 5;
        const float* col = Wo + nb * 32 + nlid;
        float s = 0.f;
        for (int k = ks * 128; k < ks * 128 + 128; k++)
            s += bv[k] * col[(size_t)k * HID];
        sm.red[tid] = s;
        __syncthreads();
        if (tid < 32) {
            float t = bo[nb * 32 + nlid];
            #pragma unroll
            for (int q = 0; q < 8; q++) t += sm.red[nlid + 32 * q];
            S_bvo[nb * 32 + nlid] = t;
        }
        __syncthreads();
    }
    gsync();

    // ===== P3: gh0 halves (96) + h1 = h2 = h0p copy =========================
    if (b < 96) {
        split_item(&sm, b, S_ginm, nullptr, HID, 0, HID,
                   Whh0, H3, bhh0, S_gh0m, S_gh0p, H3);
    } else {
        for (int i = (b - 96) * NTHR + tid; i < BSZ * HID; i += 52 * NTHR) {
            float v = S_ginm[i];
            S_h1[i] = v; S_h2[i] = v;
        }
    }
    gsync();

    // ===== P4: gh1 halves (96) ==============================================
    if (b < 96)
        split_item(&sm, b, S_ginm, nullptr, HID, 0, HID,
                   Whh1, H3, bhh1, S_gh1m, S_gh1p, H3);
    gsync();

    // ======================= time loop ======================================
    for (int t = 0; t < T; t++) {
        // GA: a = gin_eff @ Wvo + bvo   (32 items; relu(gin) except t=0)
        if (b < 32)
            split_item(&sm, b, S_ginm, S_ginp, HID, (t == 0) ? 1 : 2, HID,
                       S_Wvo, HID, S_bvo, S_a_m, S_a_p, HID);
        gsync();

        // GB: gi0 = a @ Wih0 + bih0   (96 items, A = a_m + a_p)
        if (b < 96)
            split_item(&sm, b, S_a_m, S_a_p, HID, 1, HID,
                       Wih0, H3, bih0, S_gi_m, S_gi_p, H3);
        gsync();

        // GRU0: h1 update
        gru_stage(S_gi_m, S_gi_p, S_gh0m, S_gh0p, S_h1);
        gsync();

        // GD: gi1 = h1 @ Wih1 + bih1   (96 items)
        if (b < 96)
            split_item(&sm, b, S_h1, nullptr, HID, 0, HID,
                       Wih1, H3, bih1, S_gi_m, S_gi_p, H3);
        gsync();

        // GRU1: h2 update
        gru_stage(S_gi_m, S_gi_p, S_gh1m, S_gh1p, S_h2);
        gsync();

        // GF: nz (8) + gh1_next (96) + gh0_next[0..44) (44)  = 148 items
        if (b < 8)
            split_item(&sm, b, S_h2, nullptr, HID, 0, HID,
                       Wh, LAT, bh, S_nzm, S_nzp, LAT);
        else if (b < 104)
            split_item(&sm, b - 8, S_h2, nullptr, HID, 0, HID,
                       Whh1, H3, bhh1, S_gh1m, S_gh1p, H3);
        else
            split_item(&sm, b - 104, S_h1, nullptr, HID, 0, HID,
                       Whh0, H3, bhh0, S_gh0m, S_gh0p, H3);
        gsync();

        // GG: X1 = nz_eff @ w1 + b1 (32, K=256) + gh0_next[44..96) + out copy
        if (b < 32)
            split_item(&sm, b, S_nzm, S_nzp, LAT, 1, LAT,
                       w1, HID, b1, S_X1m, S_X1p, HID);
        else if (b < 84)
            split_item(&sm, (b - 32) + 44, S_h1, nullptr, HID, 0, HID,
                       Whh0, H3, bhh0, S_gh0m, S_gh0p, H3);
        else {
            int e = (b - 84) * NTHR + tid;           // 64 blocks x 256 = 16384
            int m = e >> 8, c = e & 255;
            out[(size_t)m * ldo + (size_t)t * LAT + c] =
                S_nzm[m * LAT + c] + S_nzp[m * LAT + c];
        }
        gsync();

        // GH: gin = relu(X1_m + X1_p) @ w2 + b2   (32 items, raw partials)
        if (b < 32)
            split_item(&sm, b, S_X1m, S_X1p, HID, 2, HID,
                       w2, HID, b2, S_ginm, S_ginp, HID);
        gsync();
    }
}

// ---------------------------------------------------------------------------
extern "C" void kernel_launch(void* const* d_in, const int* in_sizes, int n_in,
                              void* d_out, int out_size)
{
    (void)in_sizes; (void)n_in;
    const float* z    = (const float*)d_in[0];
    // d_in[1] = max_len (device int32); T derived from out_size.
    const float* w1   = (const float*)d_in[2];
    const float* b1   = (const float*)d_in[3];
    const float* w2   = (const float*)d_in[4];
    const float* b2   = (const float*)d_in[5];
    // d_in[6..9] = Wq, bq, Wk, bk — dead (softmax over a single key == 1).
    const float* Wv   = (const float*)d_in[10];
    const float* bv   = (const float*)d_in[11];
    const float* Wo   = (const float*)d_in[12];
    const float* bo   = (const float*)d_in[13];
    const float* Wih0 = (const float*)d_in[14];
    const float* Whh0 = (const float*)d_in[15];
    const float* bih0 = (const float*)d_in[16];
    const float* bhh0 = (const float*)d_in[17];
    const float* Wih1 = (const float*)d_in[18];
    const float* Whh1 = (const float*)d_in[19];
    const float* bih1 = (const float*)d_in[20];
    const float* bhh1 = (const float*)d_in[21];
    const float* Wh   = (const float*)d_in[22];
    const float* bh   = (const float*)d_in[23];
    float* out = (float*)d_out;

    const int T = out_size / (BSZ * LAT);   // 128

    traj_kernel<<<NBLK, NTHR>>>(
        z, w1, b1, w2, b2, Wv, bv, Wo, bo,
        Wih0, Whh0, bih0, bhh0, Wih1, Whh1, bih1, bhh1,
        Wh, bh, out, T);
}

// round 13
// speedup vs baseline: 2.6477x; 1.2701x over previous
#include <cuda_runtime.h>
#include <cstddef>

// ---------------------------------------------------------------------------
// Persistent kernel, 64x256 tiles, fma.rn.f32x2 inner loop (128 MAC/cyc/SM),
// splitK full-chip packing, attention+GRU-input GEMM fused via Wvoih0.
// ---------------------------------------------------------------------------

#define NBLK 148
#define NTHR 256

namespace {
constexpr int HID = 1024;
constexpr int LAT = 256;
constexpr int BSZ = 64;
constexpr int H3  = 3 * HID;
constexpr size_t GI_STR  = (size_t)BSZ * H3;    // 196608
constexpr size_t GIN_STR = (size_t)BSZ * HID;   // 65536
constexpr size_t NZ_STR  = (size_t)BSZ * LAT;   // 16384
}

// -------------------- device scratch ---------------------------------------
__device__ __align__(16) float S_Wvo   [HID * HID];
__device__ __align__(16) float S_Wvoih0[(size_t)HID * H3];
__device__ __align__(16) float S_bvo   [HID];
__device__ __align__(16) float S_bvoih0[H3];
__device__ __align__(16) float S_gi [8 * BSZ * H3];
__device__ __align__(16) float S_gh0[8 * BSZ * H3];
__device__ __align__(16) float S_gh1[8 * BSZ * H3];
__device__ __align__(16) float S_gin[16 * BSZ * HID];
__device__ __align__(16) float S_X1 [8 * BSZ * HID];
__device__ __align__(16) float S_nz [8 * BSZ * LAT];
__device__ __align__(16) float S_h1 [BSZ * HID];
__device__ __align__(16) float S_h2 [BSZ * HID];

// -------------------- device-wide barrier (replay-invariant) ----------------
__device__ unsigned g_count = 0;
__device__ volatile unsigned g_gen = 0;

__device__ __forceinline__ void gsync() {
    __syncthreads();
    if (threadIdx.x == 0) {
        __threadfence();
        unsigned gen = g_gen;
        if (atomicAdd(&g_count, 1u) == NBLK - 1) {
            atomicExch(&g_count, 0u);
            __threadfence();
            g_gen = gen + 1;
        } else {
            while (g_gen == gen) { __nanosleep(32); }
        }
        __threadfence();
    }
    __syncthreads();
}

// -------------------- packed fp32x2 helpers --------------------------------
__device__ __forceinline__ float2 f2fma(float2 a, float2 b, float2 c) {
    unsigned long long ra = *reinterpret_cast<unsigned long long*>(&a);
    unsigned long long rb = *reinterpret_cast<unsigned long long*>(&b);
    unsigned long long rc = *reinterpret_cast<unsigned long long*>(&c);
    unsigned long long rd;
    asm("fma.rn.f32x2 %0, %1, %2, %3;" : "=l"(rd) : "l"(ra), "l"(rb), "l"(rc));
    return *reinterpret_cast<float2*>(&rd);
}
__device__ __forceinline__ float2 dup2(float a) {
    unsigned long long u;
    asm("mov.b64 %0, {%1, %1};" : "=l"(u) : "r"(__float_as_uint(a)));
    return *reinterpret_cast<float2*>(&u);
}
__device__ __forceinline__ float4 add4(float4 a, float4 b) {
    return make_float4(a.x + b.x, a.y + b.y, a.z + b.z, a.w + b.w);
}

// -------------------- shared memory ----------------------------------------
struct Smem {
    float As[32][72];     // [k][m]  9216 B
    float Bs[32][260];    // [k][n] 33280 B
    float red[256];
};

// ---------------------------------------------------------------------------
// One 64x256 tile: C = act(sum_p A_p)[64,Klen] @ W[Klen,256] (+bias).
// A partials: nacc buffers at stride astr.  relu applied to summed A.
// ---------------------------------------------------------------------------
__device__ __noinline__ void gemm_tile(
    Smem* sm, const float* A, size_t astr, int nacc, int lda, int Klen,
    int dorelu, const float* W, int ldw, const float* bias,
    float* C, int ldc)
{
    const int tid = threadIdx.x;
    const int tc = tid & 31, tr = tid >> 5;
    const int ml = tr * 8, nl = tc * 8;

    float2 acc[8][4];
    #pragma unroll
    for (int i = 0; i < 8; i++)
        #pragma unroll
        for (int j = 0; j < 4; j++) acc[i][j] = make_float2(0.f, 0.f);

    for (int k0 = 0; k0 < Klen; k0 += 32) {
        __syncthreads();
        // ---- stage A (64x32), transposed, summed over partials, opt relu
        #pragma unroll
        for (int r = 0; r < 2; r++) {
            int p  = tid + r * 256;            // 0..511 float4 slots
            int am = p >> 3, q = p & 7;
            const float* ap = A + (size_t)am * lda + k0 + q * 4;
            float4 v = *(const float4*)ap;
            for (int pp = 1; pp < nacc; pp++)
                v = add4(v, *(const float4*)(ap + pp * astr));
            if (dorelu) {
                v.x = fmaxf(v.x, 0.f); v.y = fmaxf(v.y, 0.f);
                v.z = fmaxf(v.z, 0.f); v.w = fmaxf(v.w, 0.f);
            }
            sm->As[q * 4 + 0][am] = v.x;
            sm->As[q * 4 + 1][am] = v.y;
            sm->As[q * 4 + 2][am] = v.z;
            sm->As[q * 4 + 3][am] = v.w;
        }
        // ---- stage B (32x256)
        #pragma unroll
        for (int i = 0; i < 8; i++) {
            int e = tid + i * 256;             // 0..2047 float4 slots
            int kr = e >> 6, c4 = e & 63;
            *(float4*)&sm->Bs[kr][c4 * 4] =
                *(const float4*)&W[(size_t)(k0 + kr) * ldw + c4 * 4];
        }
        __syncthreads();

        #pragma unroll 8
        for (int kk = 0; kk < 32; kk++) {
            float4 a0 = *(const float4*)&sm->As[kk][ml];
            float4 a1 = *(const float4*)&sm->As[kk][ml + 4];
            float2 ad[8];
            ad[0] = dup2(a0.x); ad[1] = dup2(a0.y);
            ad[2] = dup2(a0.z); ad[3] = dup2(a0.w);
            ad[4] = dup2(a1.x); ad[5] = dup2(a1.y);
            ad[6] = dup2(a1.z); ad[7] = dup2(a1.w);
            float4 b0 = *(const float4*)&sm->Bs[kk][nl];
            float4 b1 = *(const float4*)&sm->Bs[kk][nl + 4];
            float2 bp[4] = { make_float2(b0.x, b0.y), make_float2(b0.z, b0.w),
                             make_float2(b1.x, b1.y), make_float2(b1.z, b1.w) };
            #pragma unroll
            for (int i = 0; i < 8; i++)
                #pragma unroll
                for (int j = 0; j < 4; j++)
                    acc[i][j] = f2fma(ad[i], bp[j], acc[i][j]);
        }
    }

    float4 bb0 = make_float4(0.f, 0.f, 0.f, 0.f), bb1 = bb0;
    if (bias) {
        bb0 = *(const float4*)&bias[nl];
        bb1 = *(const float4*)&bias[nl + 4];
    }
    #pragma unroll
    for (int i = 0; i < 8; i++) {
        float4 v0 = make_float4(acc[i][0].x + bb0.x, acc[i][0].y + bb0.y,
                                acc[i][1].x + bb0.z, acc[i][1].y + bb0.w);
        float4 v1 = make_float4(acc[i][2].x + bb1.x, acc[i][2].y + bb1.y,
                                acc[i][3].x + bb1.z, acc[i][3].y + bb1.w);
        *(float4*)&C[(size_t)(ml + i) * ldc + nl] = v0;
        *(float4*)&C[(size_t)(ml + i) * ldc + nl + 4] = v1;
    }
}

// split-K work item j: tile = j >> lg2s, k-slice = j & (2^lg2s - 1)
__device__ __forceinline__ void do_item(
    Smem* sm, int j, int lg2s, int Ktot,
    const float* A, size_t astr, int nacc, int relu, int lda,
    const float* W, int ldw, const float* bias,
    float* Cb, size_t cstr, int ldc)
{
    const int kh = j & ((1 << lg2s) - 1);
    const int tile = j >> lg2s;
    const int Klen = Ktot >> lg2s;
    const int ko = kh * Klen;
    const int n0 = tile * 256;
    gemm_tile(sm, A + ko, astr, nacc, lda, Klen, relu,
              W + (size_t)ko * ldw + n0, ldw,
              kh ? nullptr : (bias + n0),
              Cb + kh * cstr + n0, ldc);
}

// -------------------- GRU elementwise (sums 8 partials each) ----------------
__device__ void gru_stage(const float* giB, const float* ghB, float* h)
{
    const float4* gi4 = (const float4*)giB;
    const float4* gh4 = (const float4*)ghB;
    float4* h4 = (float4*)h;
    const size_t bstr = GI_STR / 4;
    for (int i = blockIdx.x * NTHR + threadIdx.x; i < BSZ * HID / 4;
         i += NBLK * NTHR) {
        int m = i >> 8, c = i & 255;
        size_t g = (size_t)m * 768 + c;
        float4 ir = make_float4(0,0,0,0), iz = ir, in_ = ir;
        float4 hr = ir, hz = ir, hn = ir;
        #pragma unroll
        for (int p = 0; p < 8; p++) {
            size_t o = p * bstr + g;
            ir  = add4(ir,  gi4[o]);
            iz  = add4(iz,  gi4[o + 256]);
            in_ = add4(in_, gi4[o + 512]);
            hr  = add4(hr,  gh4[o]);
            hz  = add4(hz,  gh4[o + 256]);
            hn  = add4(hn,  gh4[o + 512]);
        }
        float4 hv = h4[i], res;
        {
            float r  = 1.f / (1.f + expf(-(ir.x + hr.x)));
            float zz = 1.f / (1.f + expf(-(iz.x + hz.x)));
            float nn = tanhf(in_.x + r * hn.x);
            res.x = (1.f - zz) * nn + zz * hv.x;
        }
        {
            float r  = 1.f / (1.f + expf(-(ir.y + hr.y)));
            float zz = 1.f / (1.f + expf(-(iz.y + hz.y)));
            float nn = tanhf(in_.y + r * hn.y);
            res.y = (1.f - zz) * nn + zz * hv.y;
        }
        {
            float r  = 1.f / (1.f + expf(-(ir.z + hr.z)));
            float zz = 1.f / (1.f + expf(-(iz.z + hz.z)));
            float nn = tanhf(in_.z + r * hn.z);
            res.z = (1.f - zz) * nn + zz * hv.z;
        }
        {
            float r  = 1.f / (1.f + expf(-(ir.w + hr.w)));
            float zz = 1.f / (1.f + expf(-(iz.w + hz.w)));
            float nn = tanhf(in_.w + r * hn.w);
            res.w = (1.f - zz) * nn + zz * hv.w;
        }
        h4[i] = res;
    }
}

// vector @ matrix reduction: dst[n0+lane] = sum_k v[k]*M[k,n] (+add)
__device__ void vecmat32(Smem* sm, const float* v, const float* M, int ldm,
                         const float* addv, float* dst, int n0)
{
    const int tid = threadIdx.x;
    int nl = tid & 31, ks = tid >> 5;
    const float* col = M + n0 + nl;
    float s = 0.f;
    for (int k = ks * 128; k < ks * 128 + 128; k++)
        s += v[k] * col[(size_t)k * ldm];
    sm->red[tid] = s;
    __syncthreads();
    if (tid < 32) {
        float t = addv ? addv[n0 + nl] : 0.f;
        #pragma unroll
        for (int q = 0; q < 8; q++) t += sm->red[nl + 32 * q];
        dst[n0 + nl] = t;
    }
    __syncthreads();
}

// ---------------------------------------------------------------------------
__global__ void __launch_bounds__(NTHR, 1) traj_kernel(
    const float* z,
    const float* w1, const float* b1, const float* w2, const float* b2,
    const float* Wv, const float* bv, const float* Wo, const float* bo,
    const float* Wih0, const float* Whh0, const float* bih0, const float* bhh0,
    const float* Wih1, const float* Whh1, const float* bih1, const float* bhh1,
    const float* Wh, const float* bh,
    float* out, int T)
{
    __shared__ Smem sm;
    const int b = blockIdx.x;
    const int tid = threadIdx.x;
    const int ldo = T * LAT;

    // ===== P1: Wvo tiles (64) | X1 buf0 = z@w1+b1 (4) | bvo (32) | zero =====
    if (b < 64) {
        int mi = b >> 2, ni = b & 3;
        gemm_tile(&sm, Wv + (size_t)mi * 64 * HID, 0, 1, HID, HID, 0,
                  Wo + ni * 256, HID, nullptr,
                  S_Wvo + (size_t)mi * 64 * HID + ni * 256, HID);
    } else if (b < 68) {
        int ni = b - 64;
        gemm_tile(&sm, z, 0, 1, LAT, LAT, 0,
                  w1 + ni * 256, HID, b1 + ni * 256,
                  S_X1 + ni * 256, HID);
    } else if (b < 100) {
        vecmat32(&sm, bv, Wo, HID, bo, S_bvo, (b - 68) * 32);
    } else {
        // zero gin bufs 1..15 (245760 f4) + X1 bufs 1..7 (114688 f4)
        float4* zg = (float4*)(S_gin + GIN_STR);
        float4* zx = (float4*)(S_X1 + GIN_STR);
        for (int i = (b - 100) * NTHR + tid; i < 360448; i += 48 * NTHR) {
            if (i < 245760) zg[i] = make_float4(0, 0, 0, 0);
            else            zx[i - 245760] = make_float4(0, 0, 0, 0);
        }
    }
    gsync();

    // ===== P2: Wvoih0 = Wvo @ Wih0 (192 tiles, 2 rounds) ====================
    for (int it = b; it < 192; it += NBLK) {
        int mi = it / 12, ni = it % 12;
        gemm_tile(&sm, S_Wvo + (size_t)mi * 64 * HID, 0, 1, HID, HID, 0,
                  Wih0 + ni * 256, H3, nullptr,
                  S_Wvoih0 + (size_t)mi * 64 * H3 + ni * 256, H3);
    }
    gsync();

    // ===== P3: gin buf0 = h0p = relu(sum X1)@w2+b2 (4) | bvoih0 (96) ========
    if (b < 4) {
        gemm_tile(&sm, S_X1, GIN_STR, 8, HID, HID, 1,
                  w2 + b * 256, HID, b2 + b * 256, S_gin + b * 256, HID);
    } else if (b < 100) {
        vecmat32(&sm, S_bvo, Wih0, H3, bih0, S_bvoih0, (b - 4) * 32);
    }
    gsync();

    // ===== P4: gh0 = h0p@Whh0 (96 items) | h1=h2=h0p copy ===================
    if (b < 96)
        do_item(&sm, b, 3, HID, S_gin, 0, 1, 0, HID,
                Whh0, H3, bhh0, S_gh0, GI_STR, H3);
    else {
        float4* h14 = (float4*)S_h1; float4* h24 = (float4*)S_h2;
        const float4* g4 = (const float4*)S_gin;
        for (int i = (b - 96) * NTHR + tid; i < BSZ * HID / 4; i += 52 * NTHR) {
            float4 v = g4[i]; h14[i] = v; h24[i] = v;
        }
    }
    gsync();

    // ===== P5: gh1 = h0p@Whh1 (96 items) ====================================
    if (b < 96)
        do_item(&sm, b, 3, HID, S_gin, 0, 1, 0, HID,
                Whh1, H3, bhh1, S_gh1, GI_STR, H3);
    gsync();

    // ======================= time loop ======================================
    for (int t = 0; t < T; t++) {
        // S1: gi0 = act(sum gin)@Wvoih0 + bvoih0   (96 items)
        if (b < 96)
            do_item(&sm, b, 3, HID, S_gin, GIN_STR, 16, (t != 0), HID,
                    S_Wvoih0, H3, S_bvoih0, S_gi, GI_STR, H3);
        gsync();

        gru_stage(S_gi, S_gh0, S_h1);
        gsync();

        // S2: gi1 = h1@Wih1 (96) | gh0'[0..52) = h1@Whh0 (52)
        if (b < 96)
            do_item(&sm, b, 3, HID, S_h1, 0, 1, 0, HID,
                    Wih1, H3, bih1, S_gi, GI_STR, H3);
        else
            do_item(&sm, b - 96, 3, HID, S_h1, 0, 1, 0, HID,
                    Whh0, H3, bhh0, S_gh0, GI_STR, H3);
        gsync();

        gru_stage(S_gi, S_gh1, S_h2);
        gsync();

        // S3: nz = h2@Wh (8) | gh1' = h2@Whh1 (96) | gh0'[52..96) (44)
        if (b < 8)
            do_item(&sm, b, 3, HID, S_h2, 0, 1, 0, HID,
                    Wh, LAT, bh, S_nz, NZ_STR, LAT);
        else if (b < 104)
            do_item(&sm, b - 8, 3, HID, S_h2, 0, 1, 0, HID,
                    Whh1, H3, bhh1, S_gh1, GI_STR, H3);
        else
            do_item(&sm, 52 + (b - 104), 3, HID, S_h1, 0, 1, 0, HID,
                    Whh0, H3, bhh0, S_gh0, GI_STR, H3);
        gsync();

        // S4: X1 = (sum nz)@w1+b1 (32, K=256) | out[:,t,:] copy (8 blocks)
        if (b < 32)
            do_item(&sm, b, 3, LAT, S_nz, NZ_STR, 8, 0, LAT,
                    w1, HID, b1, S_X1, GIN_STR, HID);
        else if (b < 40) {
            for (int e = (b - 32) * NTHR + tid; e < BSZ * LAT; e += 8 * NTHR) {
                float s = 0.f;
                #pragma unroll
                for (int p = 0; p < 8; p++) s += S_nz[p * NZ_STR + e];
                int m = e >> 8, c = e & 255;
                out[(size_t)m * ldo + (size_t)t * LAT + c] = s;
            }
        }
        gsync();

        // S5: gin = relu(sum X1)@w2+b2   (64 items, splitK=16)
        if (b < 64)
            do_item(&sm, b, 4, HID, S_X1, GIN_STR, 8, 1, HID,
                    w2, HID, b2, S_gin, GIN_STR, HID);
        gsync();
    }
}

// ---------------------------------------------------------------------------
extern "C" void kernel_launch(void* const* d_in, const int* in_sizes, int n_in,
                              void* d_out, int out_size)
{
    (void)in_sizes; (void)n_in;
    const float* z    = (const float*)d_in[0];
    // d_in[1] = max_len (device int32); T derived from out_size.
    const float* w1   = (const float*)d_in[2];
    const float* b1   = (const float*)d_in[3];
    const float* w2   = (const float*)d_in[4];
    const float* b2   = (const float*)d_in[5];
    // d_in[6..9] = Wq, bq, Wk, bk — dead (softmax over a single key == 1).
    const float* Wv   = (const float*)d_in[10];
    const float* bv   = (const float*)d_in[11];
    const float* Wo   = (const float*)d_in[12];
    const float* bo   = (const float*)d_in[13];
    const float* Wih0 = (const float*)d_in[14];
    const float* Whh0 = (const float*)d_in[15];
    const float* bih0 = (const float*)d_in[16];
    const float* bhh0 = (const float*)d_in[17];
    const float* Wih1 = (const float*)d_in[18];
    const float* Whh1 = (const float*)d_in[19];
    const float* bih1 = (const float*)d_in[20];
    const float* bhh1 = (const float*)d_in[21];
    const float* Wh   = (const float*)d_in[22];
    const float* bh   = (const float*)d_in[23];
    float* out = (float*)d_out;

    const int T = out_size / (BSZ * LAT);   // 128

    traj_kernel<<<NBLK, NTHR>>>(
        z, w1, b1, w2, b2, Wv, bv, Wo, bo,
        Wih0, Whh0, bih0, bhh0, Wih1, Whh1, bih1, bhh1,
        Wh, bh, out, T);
}

// round 14
// speedup vs baseline: 3.7585x; 1.4195x over previous
#include <cuda_runtime.h>
#include <cstddef>

// ---------------------------------------------------------------------------
// Persistent kernel, 64x256 tiles, conflict-free smem (XOR-swizzled A,
// contiguous B groups), fma.rn.f32x2 inner loop, register-prefetched staging,
// splitK=8 with consumer-side summation, Wvoih0 + Whw1 GEMM fusions.
// ---------------------------------------------------------------------------

#define NBLK 148
#define NTHR 256

namespace {
constexpr int HID = 1024;
constexpr int LAT = 256;
constexpr int BSZ = 64;
constexpr int H3  = 3 * HID;
constexpr size_t GI_STR  = (size_t)BSZ * H3;    // 196608
constexpr size_t GIN_STR = (size_t)BSZ * HID;   // 65536
constexpr size_t NZ_STR  = (size_t)BSZ * LAT;   // 16384
}

// -------------------- device scratch ---------------------------------------
__device__ __align__(16) float S_Wvo   [HID * HID];
__device__ __align__(16) float S_Wvoih0[(size_t)HID * H3];
__device__ __align__(16) float S_Whw1  [HID * HID];
__device__ __align__(16) float S_bvo   [HID];
__device__ __align__(16) float S_bvoih0[H3];
__device__ __align__(16) float S_bhw1b1[HID];
__device__ __align__(16) float S_gi [8 * BSZ * H3];
__device__ __align__(16) float S_gh0[8 * BSZ * H3];
__device__ __align__(16) float S_gh1[8 * BSZ * H3];
__device__ __align__(16) float S_gin[8 * BSZ * HID];
__device__ __align__(16) float S_X1 [8 * BSZ * HID];
__device__ __align__(16) float S_nz [8 * BSZ * LAT];
__device__ __align__(16) float S_h1 [BSZ * HID];
__device__ __align__(16) float S_h2 [BSZ * HID];

// -------------------- device-wide barrier (replay-invariant) ----------------
__device__ unsigned g_count = 0;
__device__ volatile unsigned g_gen = 0;

__device__ __forceinline__ void gsync() {
    __syncthreads();
    if (threadIdx.x == 0) {
        __threadfence();
        unsigned gen = g_gen;
        if (atomicAdd(&g_count, 1u) == NBLK - 1) {
            atomicExch(&g_count, 0u);
            __threadfence();
            g_gen = gen + 1;
        } else {
            while (g_gen == gen) { __nanosleep(32); }
        }
        __threadfence();
    }
    __syncthreads();
}

// -------------------- packed fp32x2 helpers --------------------------------
__device__ __forceinline__ float2 f2fma(float2 a, float2 b, float2 c) {
    unsigned long long ra = *reinterpret_cast<unsigned long long*>(&a);
    unsigned long long rb = *reinterpret_cast<unsigned long long*>(&b);
    unsigned long long rc = *reinterpret_cast<unsigned long long*>(&c);
    unsigned long long rd;
    asm("fma.rn.f32x2 %0, %1, %2, %3;" : "=l"(rd) : "l"(ra), "l"(rb), "l"(rc));
    return *reinterpret_cast<float2*>(&rd);
}
__device__ __forceinline__ float2 dup2(float a) {
    unsigned long long u;
    asm("mov.b64 %0, {%1, %1};" : "=l"(u) : "r"(__float_as_uint(a)));
    return *reinterpret_cast<float2*>(&u);
}
__device__ __forceinline__ float4 add4(float4 a, float4 b) {
    return make_float4(a.x + b.x, a.y + b.y, a.z + b.z, a.w + b.w);
}

// -------------------- shared memory ----------------------------------------
struct Smem {
    float As[32][64];     // [k][m ^ ((k>>2)<<2)]  8 KB, conflict-free
    float Bs[32][260];    // [k][n] (cols 0..255)  33.3 KB
    float red[256];
};

// ---------------------------------------------------------------------------
// One 64x256 tile: C = act(sum_{p<NACC} A_p)[64,Klen] @ W[Klen,256] (+bias).
// Thread (tc,tr): rows tr*8..+7, cols {tc*4..+3} and {128+tc*4..+3}.
// ---------------------------------------------------------------------------
template<int NACC, bool RELU>
__device__ __noinline__ void gemm_tile(
    Smem* sm, const float* A, size_t astr, int lda, int Klen,
    const float* W, int ldw, const float* bias, float* C, int ldc)
{
    const int tid = threadIdx.x;
    const int tc = tid & 31, tr = tid >> 5;
    const int ml = tr * 8;
    const int am0 = tid >> 3;            // A staging row (r=1 adds 32)
    const int kq  = tid & 7;             // A staging k-group
    const int bkr0 = tid >> 6;           // B staging k-row base (i adds 4)
    const int bc4  = (tid & 63) * 4;     // B staging col

    float2 acc[8][4];
    #pragma unroll
    for (int i = 0; i < 8; i++)
        #pragma unroll
        for (int j = 0; j < 4; j++) acc[i][j] = make_float2(0.f, 0.f);

    float4 pa[2], pb[8];
    #pragma unroll
    for (int r = 0; r < 2; r++)
        pa[r] = *(const float4*)&A[(size_t)(am0 + r * 32) * lda + kq * 4];
    #pragma unroll
    for (int i = 0; i < 8; i++)
        pb[i] = *(const float4*)&W[(size_t)(bkr0 + i * 4) * ldw + bc4];

    for (int k0 = 0; k0 < Klen; k0 += 32) {
        __syncthreads();                       // readers done with smem
        // ---- store staged A (sum partials, opt relu), XOR-swizzled cols
        #pragma unroll
        for (int r = 0; r < 2; r++) {
            const int am = am0 + r * 32;
            float4 v = pa[r];
            if (NACC > 1) {
                const float* ap = A + (size_t)am * lda + k0 + kq * 4;
                #pragma unroll
                for (int pp = 1; pp < NACC; pp++)
                    v = add4(v, *(const float4*)(ap + (size_t)pp * astr));
            }
            if (RELU) {
                v.x = fmaxf(v.x, 0.f); v.y = fmaxf(v.y, 0.f);
                v.z = fmaxf(v.z, 0.f); v.w = fmaxf(v.w, 0.f);
            }
            const int col = am ^ (kq << 2);
            sm->As[kq * 4 + 0][col] = v.x;
            sm->As[kq * 4 + 1][col] = v.y;
            sm->As[kq * 4 + 2][col] = v.z;
            sm->As[kq * 4 + 3][col] = v.w;
        }
        // ---- store staged B
        #pragma unroll
        for (int i = 0; i < 8; i++)
            *(float4*)&sm->Bs[bkr0 + i * 4][bc4] = pb[i];
        // ---- prefetch next k-tile
        if (k0 + 32 < Klen) {
            const int kn = k0 + 32;
            #pragma unroll
            for (int r = 0; r < 2; r++)
                pa[r] = *(const float4*)&A[(size_t)(am0 + r * 32) * lda + kn + kq * 4];
            #pragma unroll
            for (int i = 0; i < 8; i++)
                pb[i] = *(const float4*)&W[(size_t)(kn + bkr0 + i * 4) * ldw + bc4];
        }
        __syncthreads();                       // staged data visible

        #pragma unroll 8
        for (int kk = 0; kk < 32; kk++) {
            const int c0 = ml ^ ((kk >> 2) << 2);
            float4 a0 = *(const float4*)&sm->As[kk][c0];       // m=ml..ml+3
            float4 a1 = *(const float4*)&sm->As[kk][c0 ^ 4];   // m=ml+4..+7
            float2 ad[8];
            ad[0] = dup2(a0.x); ad[1] = dup2(a0.y);
            ad[2] = dup2(a0.z); ad[3] = dup2(a0.w);
            ad[4] = dup2(a1.x); ad[5] = dup2(a1.y);
            ad[6] = dup2(a1.z); ad[7] = dup2(a1.w);
            float4 b0 = *(const float4*)&sm->Bs[kk][tc * 4];
            float4 b1 = *(const float4*)&sm->Bs[kk][128 + tc * 4];
            float2 bp[4] = { make_float2(b0.x, b0.y), make_float2(b0.z, b0.w),
                             make_float2(b1.x, b1.y), make_float2(b1.z, b1.w) };
            #pragma unroll
            for (int i = 0; i < 8; i++)
                #pragma unroll
                for (int j = 0; j < 4; j++)
                    acc[i][j] = f2fma(ad[i], bp[j], acc[i][j]);
        }
    }

    float4 bb0 = make_float4(0.f, 0.f, 0.f, 0.f), bb1 = bb0;
    if (bias) {
        bb0 = *(const float4*)&bias[tc * 4];
        bb1 = *(const float4*)&bias[128 + tc * 4];
    }
    #pragma unroll
    for (int i = 0; i < 8; i++) {
        float4 v0 = make_float4(acc[i][0].x + bb0.x, acc[i][0].y + bb0.y,
                                acc[i][1].x + bb0.z, acc[i][1].y + bb0.w);
        float4 v1 = make_float4(acc[i][2].x + bb1.x, acc[i][2].y + bb1.y,
                                acc[i][3].x + bb1.z, acc[i][3].y + bb1.w);
        *(float4*)&C[(size_t)(ml + i) * ldc + tc * 4] = v0;
        *(float4*)&C[(size_t)(ml + i) * ldc + 128 + tc * 4] = v1;
    }
}

// split-K work item j: tile = j>>lg2s (n0 = tile*256), slice = j&mask
template<int NACC, bool RELU>
__device__ __forceinline__ void do_item(
    Smem* sm, int j, int lg2s, int Ktot,
    const float* A, size_t astr, int lda,
    const float* W, int ldw, const float* bias,
    float* Cb, size_t cstr, int ldc)
{
    const int kh = j & ((1 << lg2s) - 1);
    const int n0 = (j >> lg2s) * 256;
    const int Klen = Ktot >> lg2s;
    const int ko = kh * Klen;
    gemm_tile<NACC, RELU>(sm, A + ko, astr, lda, Klen,
                          W + (size_t)ko * ldw + n0, ldw,
                          kh ? nullptr : (bias + n0),
                          Cb + kh * cstr + n0, ldc);
}

// -------------------- GRU elementwise (sums 8 partials) ---------------------
__device__ void gru_stage(const float* giB, const float* ghB, float* h)
{
    const float4* gi4 = (const float4*)giB;
    const float4* gh4 = (const float4*)ghB;
    float4* h4 = (float4*)h;
    const size_t bstr = GI_STR / 4;
    for (int i = blockIdx.x * NTHR + threadIdx.x; i < BSZ * HID / 4;
         i += NBLK * NTHR) {
        int m = i >> 8, c = i & 255;
        size_t g = (size_t)m * 768 + c;
        float4 ir = make_float4(0,0,0,0), iz = ir, in_ = ir;
        float4 hr = ir, hz = ir, hn = ir;
        #pragma unroll
        for (int p = 0; p < 8; p++) {
            size_t o = p * bstr + g;
            ir  = add4(ir,  gi4[o]);
            iz  = add4(iz,  gi4[o + 256]);
            in_ = add4(in_, gi4[o + 512]);
            hr  = add4(hr,  gh4[o]);
            hz  = add4(hz,  gh4[o + 256]);
            hn  = add4(hn,  gh4[o + 512]);
        }
        float4 hv = h4[i], res;
        res.x = [&]{ float r=1.f/(1.f+expf(-(ir.x+hr.x)));
                     float zz=1.f/(1.f+expf(-(iz.x+hz.x)));
                     float nn=tanhf(in_.x+r*hn.x);
                     return (1.f-zz)*nn+zz*hv.x; }();
        res.y = [&]{ float r=1.f/(1.f+expf(-(ir.y+hr.y)));
                     float zz=1.f/(1.f+expf(-(iz.y+hz.y)));
                     float nn=tanhf(in_.y+r*hn.y);
                     return (1.f-zz)*nn+zz*hv.y; }();
        res.z = [&]{ float r=1.f/(1.f+expf(-(ir.z+hr.z)));
                     float zz=1.f/(1.f+expf(-(iz.z+hz.z)));
                     float nn=tanhf(in_.z+r*hn.z);
                     return (1.f-zz)*nn+zz*hv.z; }();
        res.w = [&]{ float r=1.f/(1.f+expf(-(ir.w+hr.w)));
                     float zz=1.f/(1.f+expf(-(iz.w+hz.w)));
                     float nn=tanhf(in_.w+r*hn.w);
                     return (1.f-zz)*nn+zz*hv.w; }();
        h4[i] = res;
    }
}

// vector @ matrix: dst[n0+lane] = sum_k v[k]*M[k,n] (+addv)
__device__ void vecmatK(Smem* sm, const float* v, const float* M, int ldm,
                        int K, const float* addv, float* dst, int n0)
{
    const int tid = threadIdx.x;
    int nl = tid & 31, ks = tid >> 5;
    const int seg = K >> 3;
    const float* col = M + n0 + nl;
    float s = 0.f;
    for (int k = ks * seg; k < ks * seg + seg; k++)
        s += v[k] * col[(size_t)k * ldm];
    sm->red[tid] = s;
    __syncthreads();
    if (tid < 32) {
        float t = addv ? addv[n0 + nl] : 0.f;
        #pragma unroll
        for (int q = 0; q < 8; q++) t += sm->red[nl + 32 * q];
        dst[n0 + nl] = t;
    }
    __syncthreads();
}

// ---------------------------------------------------------------------------
__global__ void __launch_bounds__(NTHR, 1) traj_kernel(
    const float* z,
    const float* w1, const float* b1, const float* w2, const float* b2,
    const float* Wv, const float* bv, const float* Wo, const float* bo,
    const float* Wih0, const float* Whh0, const float* bih0, const float* bhh0,
    const float* Wih1, const float* Whh1, const float* bih1, const float* bhh1,
    const float* Wh, const float* bh,
    float* out, int T)
{
    __shared__ Smem sm;
    const int b = blockIdx.x;
    const int tid = threadIdx.x;
    const int ldo = T * LAT;

    // ===== P1: Wvo (64) | X1z (4) | bvo (32) | bhw1b1 (32) | zero X1 1..7 ===
    if (b < 64) {
        int mi = b >> 2, ni = b & 3;
        gemm_tile<1, false>(&sm, Wv + (size_t)mi * 64 * HID, 0, HID, HID,
                            Wo + ni * 256, HID, nullptr,
                            S_Wvo + (size_t)mi * 64 * HID + ni * 256, HID);
    } else if (b < 68) {
        int ni = b - 64;
        gemm_tile<1, false>(&sm, z, 0, LAT, LAT,
                            w1 + ni * 256, HID, b1 + ni * 256,
                            S_X1 + ni * 256, HID);
    } else if (b < 100) {
        vecmatK(&sm, bv, Wo, HID, HID, bo, S_bvo, (b - 68) * 32);
    } else if (b < 132) {
        vecmatK(&sm, bh, w1, HID, LAT, b1, S_bhw1b1, (b - 100) * 32);
    } else {
        float4* zx = (float4*)(S_X1 + GIN_STR);       // bufs 1..7
        for (int i = (b - 132) * NTHR + tid; i < 114688; i += 16 * NTHR)
            zx[i] = make_float4(0.f, 0.f, 0.f, 0.f);
    }
    gsync();

    // ===== P2: Wvoih0 = Wvo@Wih0 (192) + Whw1 = Wh@w1 (64) ==================
    for (int it = b; it < 256; it += NBLK) {
        if (it < 192) {
            int mi = it / 12, ni = it % 12;
            gemm_tile<1, false>(&sm, S_Wvo + (size_t)mi * 64 * HID, 0, HID, HID,
                                Wih0 + ni * 256, H3, nullptr,
                                S_Wvoih0 + (size_t)mi * 64 * H3 + ni * 256, H3);
        } else {
            int j = it - 192, mi = j >> 2, ni = j & 3;
            gemm_tile<1, false>(&sm, Wh + (size_t)mi * 64 * LAT, 0, LAT, LAT,
                                w1 + ni * 256, HID, nullptr,
                                S_Whw1 + (size_t)mi * 64 * HID + ni * 256, HID);
        }
    }
    gsync();

    // ===== P3: gin = relu(sum X1z)@w2+b2 (32 items) | bvoih0 (96) ===========
    if (b < 32)
        do_item<8, true>(&sm, b, 3, HID, S_X1, GIN_STR, HID,
                         w2, HID, b2, S_gin, GIN_STR, HID);
    else if (b < 128)
        vecmatK(&sm, S_bvo, Wih0, H3, HID, bih0, S_bvoih0, (b - 32) * 32);
    gsync();

    // ===== P4: gh0 = h0p@Whh0 (96, A = sum gin) | h1=h2=sum gin =============
    if (b < 96)
        do_item<8, false>(&sm, b, 3, HID, S_gin, GIN_STR, HID,
                          Whh0, H3, bhh0, S_gh0, GI_STR, H3);
    else {
        float4* h14 = (float4*)S_h1; float4* h24 = (float4*)S_h2;
        const float4* g4 = (const float4*)S_gin;
        for (int i = (b - 96) * NTHR + tid; i < BSZ * HID / 4; i += 52 * NTHR) {
            float4 v = g4[i];
            #pragma unroll
            for (int p = 1; p < 8; p++) v = add4(v, g4[p * (GIN_STR / 4) + i]);
            h14[i] = v; h24[i] = v;
        }
    }
    gsync();

    // ======================= time loop ======================================
    for (int t = 0; t < T; t++) {
        // S1: gi0 = act(sum gin)@Wvoih0+bvoih0 (96) | gh1' = h2@Whh1 (52)
        if (b < 96) {
            if (t == 0)
                do_item<8, false>(&sm, b, 3, HID, S_gin, GIN_STR, HID,
                                  S_Wvoih0, H3, S_bvoih0, S_gi, GI_STR, H3);
            else
                do_item<8, true>(&sm, b, 3, HID, S_gin, GIN_STR, HID,
                                 S_Wvoih0, H3, S_bvoih0, S_gi, GI_STR, H3);
        } else {
            do_item<1, false>(&sm, b - 96, 3, HID, S_h2, 0, HID,
                              Whh1, H3, bhh1, S_gh1, GI_STR, H3);
        }
        gsync();

        gru_stage(S_gi, S_gh0, S_h1);
        gsync();

        // S2: gi1 = h1@Wih1 (96) | gh1' rest (44) | gh0' (8)
        if (b < 96)
            do_item<1, false>(&sm, b, 3, HID, S_h1, 0, HID,
                              Wih1, H3, bih1, S_gi, GI_STR, H3);
        else if (b < 140)
            do_item<1, false>(&sm, 52 + (b - 96), 3, HID, S_h2, 0, HID,
                              Whh1, H3, bhh1, S_gh1, GI_STR, H3);
        else
            do_item<1, false>(&sm, b - 140, 3, HID, S_h1, 0, HID,
                              Whh0, H3, bhh0, S_gh0, GI_STR, H3);
        gsync();

        gru_stage(S_gi, S_gh1, S_h2);
        gsync();

        // S3: nz = h2@Wh (8) | X1 = h2@Whw1+bhw1b1 (32) | gh0' rest (88)
        if (b < 8)
            do_item<1, false>(&sm, b, 3, HID, S_h2, 0, HID,
                              Wh, LAT, bh, S_nz, NZ_STR, LAT);
        else if (b < 40)
            do_item<1, false>(&sm, b - 8, 3, HID, S_h2, 0, HID,
                              S_Whw1, HID, S_bhw1b1, S_X1, GIN_STR, HID);
        else if (b < 128)
            do_item<1, false>(&sm, 8 + (b - 40), 3, HID, S_h1, 0, HID,
                              Whh0, H3, bhh0, S_gh0, GI_STR, H3);
        gsync();

        // S4: gin = relu(sum X1)@w2+b2 (32) | out[:,t,:] = sum nz (8)
        if (b < 32)
            do_item<8, true>(&sm, b, 3, HID, S_X1, GIN_STR, HID,
                             w2, HID, b2, S_gin, GIN_STR, HID);
        else if (b < 40) {
            for (int e = (b - 32) * NTHR + tid; e < BSZ * LAT; e += 8 * NTHR) {
                float s = 0.f;
                #pragma unroll
                for (int p = 0; p < 8; p++) s += S_nz[p * NZ_STR + e];
                int m = e >> 8, c = e & 255;
                out[(size_t)m * ldo + (size_t)t * LAT + c] = s;
            }
        }
        gsync();
    }
}

// ---------------------------------------------------------------------------
extern "C" void kernel_launch(void* const* d_in, const int* in_sizes, int n_in,
                              void* d_out, int out_size)
{
    (void)in_sizes; (void)n_in;
    const float* z    = (const float*)d_in[0];
    // d_in[1] = max_len (device int32); T derived from out_size.
    const float* w1   = (const float*)d_in[2];
    const float* b1   = (const float*)d_in[3];
    const float* w2   = (const float*)d_in[4];
    const float* b2   = (const float*)d_in[5];
    // d_in[6..9] = Wq, bq, Wk, bk — dead (softmax over a single key == 1).
    const float* Wv   = (const float*)d_in[10];
    const float* bv   = (const float*)d_in[11];
    const float* Wo   = (const float*)d_in[12];
    const float* bo   = (const float*)d_in[13];
    const float* Wih0 = (const float*)d_in[14];
    const float* Whh0 = (const float*)d_in[15];
    const float* bih0 = (const float*)d_in[16];
    const float* bhh0 = (const float*)d_in[17];
    const float* Wih1 = (const float*)d_in[18];
    const float* Whh1 = (const float*)d_in[19];
    const float* bih1 = (const float*)d_in[20];
    const float* bhh1 = (const float*)d_in[21];
    const float* Wh   = (const float*)d_in[22];
    const float* bh   = (const float*)d_in[23];
    float* out = (float*)d_out;

    const int T = out_size / (BSZ * LAT);   // 128

    traj_kernel<<<NBLK, NTHR>>>(
        z, w1, b1, w2, b2, Wv, bv, Wo, bo,
        Wih0, Whh0, bih0, bhh0, Wih1, Whh1, bih1, bhh1,
        Wh, bh, out, T);
}